// round 15
// baseline (speedup 1.0000x reference)
#include <cuda_runtime.h>
#include <math.h>
#include <stdint.h>

#define BB 32
#define CC 273
#define TT 4096
#define OO 270
#define DD 242
#define NF 11
#define C_PAD 288   // padded C stride for embT
#define O_PAD 272   // padded O stride for hT / weights

// Scratch (device globals: allocation-free). Generous pads cover tile-edge
// cp.async address formation on the padded K/M/N ranges.
__device__ __align__(16) float g_embT[(size_t)BB * DD * C_PAD + 8192]; // [b][d][c]
__device__ __align__(16) float g_hT  [(size_t)BB * DD * O_PAD + 8192]; // [b][d][o]
__device__ __align__(16) float g_w   [(size_t)BB * CC * O_PAD + 16384]; // [b][c][o]
__device__ float g_off[(size_t)BB * CC];

__device__ __forceinline__ uint32_t f2tf32(float f) {
    uint32_t r;
    asm("cvt.rna.tf32.f32 %0, %1;" : "=r"(r) : "f"(f));
    return r;
}

__device__ __forceinline__ void cp16(uint32_t dst, const void* src, bool pred) {
    int sz = pred ? 16 : 0;
    asm volatile("cp.async.cg.shared.global [%0], [%1], 16, %2;"
                 :: "r"(dst), "l"(src), "r"(sz) : "memory");
}

#define MMA_TF32(acc, a0, a1, a2, a3, b0, b1)                                \
    asm volatile(                                                            \
        "mma.sync.aligned.m16n8k8.row.col.f32.tf32.tf32.f32 "                \
        "{%0,%1,%2,%3}, {%4,%5,%6,%7}, {%8,%9}, {%0,%1,%2,%3};"              \
        : "+f"((acc)[0]), "+f"((acc)[1]), "+f"((acc)[2]), "+f"((acc)[3])     \
        : "r"(a0), "r"(a1), "r"(a2), "r"(a3), "r"(b0), "r"(b1))

// ---------------------------------------------------------------------------
// Kernel 1: Fourier embedding, transposed [b][d][c], + invalid offset
// ---------------------------------------------------------------------------
__global__ void embed_kernel(const float* __restrict__ pos) {
    int b = blockIdx.y;
    int c = blockIdx.x * 32 + threadIdx.x;
    if (c >= CC) return;
    float x = pos[((size_t)b * CC + c) * 2 + 0];
    float y = pos[((size_t)b * CC + c) * 2 + 1];
    if (threadIdx.y == 0) {
        g_off[(size_t)b * CC + c] = (x == -0.1f && y == -0.1f) ? -1e9f : 0.0f;
    }
    const float scale = (float)(2.0 * 3.14159265358979323846 / 1.4);
    float px = x + 0.2f, py = y + 0.2f;
    float* eb = g_embT + (size_t)b * (DD * C_PAD);
    for (int k = threadIdx.y; k < NF * NF; k += blockDim.y) {
        int i = k / NF, j = k % NF;
        float loc = px * (scale * (float)i) + py * (scale * (float)j);
        float s, co;
        sincosf(loc, &s, &co);
        eb[(size_t)k * C_PAD + c] = co;
        eb[(size_t)(NF * NF + k) * C_PAD + c] = s;
    }
}

// ---------------------------------------------------------------------------
// Kernel 2: heads gather + transpose -> hT[b][d][o]
// ---------------------------------------------------------------------------
__global__ void gather_heads_kernel(const float* __restrict__ heads,
                                    const int* __restrict__ subj) {
    __shared__ float tile[32][33];
    int b = blockIdx.z;
    int s = subj[b];
    int d0 = blockIdx.x * 32;
    int o0 = blockIdx.y * 32;
    const float* hb = heads + (size_t)s * OO * DD;
    for (int oy = threadIdx.y; oy < 32; oy += blockDim.y) {
        int o = o0 + oy;
        int d = d0 + threadIdx.x;
        tile[oy][threadIdx.x] = (o < OO && d < DD) ? hb[(size_t)o * DD + d] : 0.0f;
    }
    __syncthreads();
    float* ht = g_hT + (size_t)b * (DD * O_PAD);
    for (int dy = threadIdx.y; dy < 32; dy += blockDim.y) {
        int d = d0 + dy;
        int o = o0 + threadIdx.x;
        if (d < DD && o < OO) ht[(size_t)d * O_PAD + o] = tile[threadIdx.x][dy];
    }
}

// ---------------------------------------------------------------------------
// Kernel 3: scores via 3xTF32 tensor cores (fp32-class accuracy).
// g_w[b][c][o] = sum_d embT[b][d][c] * hT[b][d][o] + off[b][c]
// ---------------------------------------------------------------------------
#define S_BM 64
#define S_BN 64
#define S_BK 16
#define S_STR 72
#define S_NT ((DD + S_BK - 1) / S_BK)   // 16

__global__ __launch_bounds__(128) void scores_kernel(
    const float* __restrict__ A, const float* __restrict__ B,
    float* __restrict__ C, const float* __restrict__ off) {
    __shared__ uint32_t As[3][S_BK][S_STR];
    __shared__ uint32_t Bs[3][S_BK][S_STR];

    int b = blockIdx.z;
    const float* Ab = A + (size_t)b * ((size_t)DD * C_PAD);
    const float* Bb = B + (size_t)b * ((size_t)DD * O_PAD);
    float* Cb = C + (size_t)b * ((size_t)CC * O_PAD);

    int m0 = blockIdx.y * S_BM;
    int n0 = blockIdx.x * S_BN;
    int tid = threadIdx.x;
    int warpId = tid >> 5;
    int lane = tid & 31;
    int warpM = warpId & 1;
    int warpN = warpId >> 1;
    int groupID = lane >> 2;
    int tig = lane & 3;

    int kq[2], mq[2];
#pragma unroll
    for (int r = 0; r < 2; r++) {
        int ia = (tid + r * 128) * 4;
        kq[r] = ia / S_BM; mq[r] = ia % S_BM;
    }

    float acc[2][4][4];
#pragma unroll
    for (int mt = 0; mt < 2; mt++)
#pragma unroll
        for (int nt = 0; nt < 4; nt++)
#pragma unroll
            for (int r = 0; r < 4; r++) acc[mt][nt][r] = 0.0f;

    auto issue = [&](int kt, int stage) {
        int k0 = kt * S_BK;
#pragma unroll
        for (int r = 0; r < 2; r++) {
            bool p = (k0 + kq[r]) < DD;
            cp16(__cvta_generic_to_shared(&As[stage][kq[r]][mq[r]]),
                 Ab + (size_t)(k0 + kq[r]) * C_PAD + m0 + mq[r], p);
            cp16(__cvta_generic_to_shared(&Bs[stage][kq[r]][mq[r]]),
                 Bb + (size_t)(k0 + kq[r]) * O_PAD + n0 + mq[r], p);
        }
    };

    issue(0, 0);
    asm volatile("cp.async.commit_group;" ::: "memory");
    issue(1, 1);
    asm volatile("cp.async.commit_group;" ::: "memory");

    for (int kt = 0; kt < S_NT; kt++) {
        int stage = kt % 3;
        if (kt + 2 < S_NT) issue(kt + 2, (kt + 2) % 3);
        asm volatile("cp.async.commit_group;" ::: "memory");
        asm volatile("cp.async.wait_group 2;" ::: "memory");
        __syncthreads();

#pragma unroll
        for (int kk = 0; kk < S_BK; kk += 8) {
            uint32_t aB[2][4], aS[2][4];
#pragma unroll
            for (int mt = 0; mt < 2; mt++) {
                int mb = warpM * 32 + mt * 16;
#pragma unroll
                for (int q = 0; q < 4; q++) {
                    int kr = kk + tig + (q >> 1) * 4;
                    int mc = mb + groupID + (q & 1) * 8;
                    float x = __uint_as_float(As[stage][kr][mc]);
                    uint32_t big = f2tf32(x);
                    aB[mt][q] = big;
                    aS[mt][q] = f2tf32(x - __uint_as_float(big));
                }
            }
            uint32_t bB[4][2], bS[4][2];
#pragma unroll
            for (int nt = 0; nt < 4; nt++) {
                int nb = warpN * 32 + nt * 8;
#pragma unroll
                for (int q = 0; q < 2; q++) {
                    float x = __uint_as_float(Bs[stage][kk + tig + q * 4][nb + groupID]);
                    uint32_t big = f2tf32(x);
                    bB[nt][q] = big;
                    bS[nt][q] = f2tf32(x - __uint_as_float(big));
                }
            }
#pragma unroll
            for (int mt = 0; mt < 2; mt++)
#pragma unroll
                for (int nt = 0; nt < 4; nt++) {
                    MMA_TF32(acc[mt][nt], aB[mt][0], aB[mt][1], aB[mt][2], aB[mt][3],
                             bS[nt][0], bS[nt][1]);
                    MMA_TF32(acc[mt][nt], aS[mt][0], aS[mt][1], aS[mt][2], aS[mt][3],
                             bB[nt][0], bB[nt][1]);
                    MMA_TF32(acc[mt][nt], aB[mt][0], aB[mt][1], aB[mt][2], aB[mt][3],
                             bB[nt][0], bB[nt][1]);
                }
        }
        __syncthreads();
    }

#pragma unroll
    for (int mt = 0; mt < 2; mt++) {
        int mrow0 = m0 + warpM * 32 + mt * 16 + groupID;
#pragma unroll
        for (int nt = 0; nt < 4; nt++) {
            int ncol = n0 + warpN * 32 + nt * 8 + tig * 2;
#pragma unroll
            for (int h = 0; h < 2; h++) {
                int m = mrow0 + h * 8;
                if (m < CC) {
                    float ofs = off[(size_t)b * CC + m];
                    if (ncol < OO)
                        Cb[(size_t)m * O_PAD + ncol] = acc[mt][nt][h * 2] + ofs;
                    if (ncol + 1 < OO)
                        Cb[(size_t)m * O_PAD + ncol + 1] = acc[mt][nt][h * 2 + 1] + ofs;
                }
            }
        }
    }
}

// ---------------------------------------------------------------------------
// Kernel 4: softmax over c per (b,o), in place. Block (32 o, 32 c-slices).
// Weights written PRE-ROUNDED to tf32 (A operand of big GEMM passes raw).
// ---------------------------------------------------------------------------
__global__ __launch_bounds__(1024) void softmax_kernel() {
    __shared__ float red[32][33];
    int b = blockIdx.y;
    int tx = threadIdx.x;
    int ty = threadIdx.y;
    int o = blockIdx.x * 32 + tx;
    bool active = (o < OO);
    float* col = g_w + (size_t)b * (CC * O_PAD) + (active ? o : 0);

    float mx = -3.0e38f;
#pragma unroll
    for (int c = ty; c < CC; c += 32)
        if (active) mx = fmaxf(mx, col[(size_t)c * O_PAD]);
    red[ty][tx] = mx;
    __syncthreads();
    if (ty == 0) {
#pragma unroll
        for (int r = 1; r < 32; r++) mx = fmaxf(mx, red[r][tx]);
        red[0][tx] = mx;
    }
    __syncthreads();
    mx = red[0][tx];
    __syncthreads();

    float s = 0.0f;
    float e_loc[9];                // ceil(273/32) = 9
    int ns = 0;
#pragma unroll
    for (int c = ty; c < CC; c += 32) {
        if (active) {
            float e = expf(col[(size_t)c * O_PAD] - mx);
            e_loc[ns] = e;
            s += e;
        }
        ns++;
    }
    red[ty][tx] = s;
    __syncthreads();
    if (ty == 0) {
#pragma unroll
        for (int r = 1; r < 32; r++) s += red[r][tx];
        red[0][tx] = 1.0f / s;
    }
    __syncthreads();
    float inv = red[0][tx];

    ns = 0;
#pragma unroll
    for (int c = ty; c < CC; c += 32) {
        if (active)
            col[(size_t)c * O_PAD] = __uint_as_float(f2tf32(e_loc[ns] * inv));
        ns++;
    }
}

// ---------------------------------------------------------------------------
// Kernel 5: TF32 tensor-core GEMM, 3-stage cp.async, FULL-M block tile.
// out[b][m][n] = sum_k w[b][k][m] * meg[b][k][n]; M=270,N=4096,K=273.
// BM=288 (one m-tile: meg read ONCE from L2 instead of 3x), BN=128, BK=16.
// 384 thr = 12 warps (3M x 4N); warp tile 96x32 (6x4 m16n8k8) — identical
// inner loop to the measured-good BM=96 kernel. Dynamic SMEM 82.9 KB.
// Strides 296/136 (≡8 mod 32): conflict-free fragment LDS.
// ---------------------------------------------------------------------------
#define TBM 288
#define TBN 128
#define TBK 16
#define A_STR 296
#define B_STR 136
#define NTILES ((CC + TBK - 1) / TBK)   // 18
#define A_U32S (3 * TBK * A_STR)        // 14208 u32
#define GEMM_SMEM_BYTES ((A_U32S + 3 * TBK * B_STR) * 4)  // 82944 B

__global__ __launch_bounds__(384, 1) void gemm_tf32_kernel(
    const float* __restrict__ A, const float* __restrict__ B,
    float* __restrict__ C) {
    extern __shared__ uint32_t smem[];
    uint32_t* Asm = smem;                 // [3][TBK][A_STR]
    uint32_t* Bsm = smem + A_U32S;        // [3][TBK][B_STR]

    int b = blockIdx.z;
    const float* Ab = A + (size_t)b * ((size_t)CC * O_PAD);
    const float* Bb = B + (size_t)b * ((size_t)CC * TT);
    float* Cb = C + (size_t)b * ((size_t)OO * TT);

    int n0 = blockIdx.x * TBN;
    int tid = threadIdx.x;
    int warpId = tid >> 5;
    int lane = tid & 31;
    int warpN = warpId & 3;        // 4 warps along N
    int warpM = warpId >> 2;       // 3 warps along M (3*96=288)
    int groupID = lane >> 2;
    int tig = lane & 3;

    // Fill coords. A: 288*16=4608 fl = 1152 vec4 = 3 chunks of 384.
    // B: 128*16=2048 fl = 512 vec4: chunk0 all 384 thr, chunk1 first 128.
    int ka[3], ma[3];
#pragma unroll
    for (int r = 0; r < 3; r++) {
        int ia = (tid + r * 384) * 4;
        ka[r] = ia / TBM; ma[r] = ia % TBM;
    }
    int kb0 = (tid * 4) / TBN, nb0 = (tid * 4) % TBN;
    bool b1Fill = (tid < 128);
    int ib1 = (tid + 384) * 4;
    int kb1 = ib1 / TBN, nb1 = ib1 % TBN;

    float acc[6][4][4];
#pragma unroll
    for (int mt = 0; mt < 6; mt++)
#pragma unroll
        for (int nt = 0; nt < 4; nt++)
#pragma unroll
            for (int r = 0; r < 4; r++) acc[mt][nt][r] = 0.0f;

    auto issue_tile = [&](int kt, int stage) {
        int k0 = kt * TBK;
        uint32_t* As = Asm + stage * (TBK * A_STR);
        uint32_t* Bs = Bsm + stage * (TBK * B_STR);
#pragma unroll
        for (int r = 0; r < 3; r++)
            cp16(__cvta_generic_to_shared(&As[ka[r] * A_STR + ma[r]]),
                 Ab + (size_t)(k0 + ka[r]) * O_PAD + ma[r], (k0 + ka[r]) < CC);
        cp16(__cvta_generic_to_shared(&Bs[kb0 * B_STR + nb0]),
             Bb + (size_t)(k0 + kb0) * TT + n0 + nb0, (k0 + kb0) < CC);
        if (b1Fill)
            cp16(__cvta_generic_to_shared(&Bs[kb1 * B_STR + nb1]),
                 Bb + (size_t)(k0 + kb1) * TT + n0 + nb1, (k0 + kb1) < CC);
    };

    issue_tile(0, 0);
    asm volatile("cp.async.commit_group;" ::: "memory");
    issue_tile(1, 1);
    asm volatile("cp.async.commit_group;" ::: "memory");

    for (int kt = 0; kt < NTILES; kt++) {
        int stage = kt % 3;
        if (kt + 2 < NTILES) issue_tile(kt + 2, (kt + 2) % 3);
        asm volatile("cp.async.commit_group;" ::: "memory");
        asm volatile("cp.async.wait_group 2;" ::: "memory");
        __syncthreads();

        const uint32_t* As = Asm + stage * (TBK * A_STR);
        const uint32_t* Bs = Bsm + stage * (TBK * B_STR);

#pragma unroll
        for (int kk = 0; kk < TBK; kk += 8) {
            uint32_t afrag[6][4];
#pragma unroll
            for (int mt = 0; mt < 6; mt++) {
                int mb = warpM * 96 + mt * 16;
                afrag[mt][0] = As[(kk + tig) * A_STR + mb + groupID];
                afrag[mt][1] = As[(kk + tig) * A_STR + mb + groupID + 8];
                afrag[mt][2] = As[(kk + tig + 4) * A_STR + mb + groupID];
                afrag[mt][3] = As[(kk + tig + 4) * A_STR + mb + groupID + 8];
            }
            uint32_t bfrag[4][2];
#pragma unroll
            for (int nt = 0; nt < 4; nt++) {
                int nbase = warpN * 32 + nt * 8;
                bfrag[nt][0] = f2tf32(__uint_as_float(Bs[(kk + tig) * B_STR + nbase + groupID]));
                bfrag[nt][1] = f2tf32(__uint_as_float(Bs[(kk + tig + 4) * B_STR + nbase + groupID]));
            }
#pragma unroll
            for (int mt = 0; mt < 6; mt++)
#pragma unroll
                for (int nt = 0; nt < 4; nt++)
                    MMA_TF32(acc[mt][nt], afrag[mt][0], afrag[mt][1],
                             afrag[mt][2], afrag[mt][3],
                             bfrag[nt][0], bfrag[nt][1]);
        }
        __syncthreads();
    }

    // Epilogue
#pragma unroll
    for (int mt = 0; mt < 6; mt++) {
        int mrow0 = warpM * 96 + mt * 16 + groupID;
#pragma unroll
        for (int nt = 0; nt < 4; nt++) {
            int ncol = n0 + warpN * 32 + nt * 8 + tig * 2;
            if (mrow0 < OO) {
                float2 v = make_float2(acc[mt][nt][0], acc[mt][nt][1]);
                *(float2*)(Cb + (size_t)mrow0 * TT + ncol) = v;
            }
            if (mrow0 + 8 < OO) {
                float2 v = make_float2(acc[mt][nt][2], acc[mt][nt][3]);
                *(float2*)(Cb + (size_t)(mrow0 + 8) * TT + ncol) = v;
            }
        }
    }
}

// ---------------------------------------------------------------------------

extern "C" void kernel_launch(void* const* d_in, const int* in_sizes, int n_in,
                              void* d_out, int out_size) {
    const float* meg   = (const float*)d_in[0];   // [B,C,T]
    const float* pos   = (const float*)d_in[1];   // [B,C,2]
    const int*   subj  = (const int*)d_in[2];     // [B]
    const float* heads = (const float*)d_in[3];   // [200,O,D]
    float* out = (float*)d_out;                   // [B,O,T]

    float *p_embT, *p_hT, *p_w, *p_off;
    cudaGetSymbolAddress((void**)&p_embT, g_embT);
    cudaGetSymbolAddress((void**)&p_hT,   g_hT);
    cudaGetSymbolAddress((void**)&p_w,    g_w);
    cudaGetSymbolAddress((void**)&p_off,  g_off);

    // Opt in to >48KB dynamic SMEM for the big GEMM (idempotent; not a
    // stream op, so graph capture is unaffected).
    cudaFuncSetAttribute(gemm_tf32_kernel,
                         cudaFuncAttributeMaxDynamicSharedMemorySize,
                         GEMM_SMEM_BYTES);

    // 1) Fourier embedding (transposed) + invalid offsets
    embed_kernel<<<dim3((CC + 31) / 32, BB), dim3(32, 8)>>>(pos);

    // 2) heads gather + transpose
    gather_heads_kernel<<<dim3((DD + 31) / 32, (OO + 31) / 32, BB), dim3(32, 8)>>>(heads, subj);

    // 3) scores via 3xTF32 tensor cores
    scores_kernel<<<dim3((OO + S_BN - 1) / S_BN, (CC + S_BM - 1) / S_BM, BB), 128>>>(
        p_embT, p_hT, p_w, p_off);

    // 4) softmax over c per (b,o), weights written tf32-rounded
    softmax_kernel<<<dim3((OO + 31) / 32, BB), dim3(32, 32)>>>();

    // 5) out[b][o][t] = sum_c w[b][c][o] * meg[b][c][t]  -- TF32, full-M tile
    gemm_tf32_kernel<<<dim3(TT / TBN, 1, BB), 384, GEMM_SMEM_BYTES>>>(
        p_w, meg, out);
}

// round 16
// speedup vs baseline: 1.1816x; 1.1816x over previous
#include <cuda_runtime.h>
#include <math.h>
#include <stdint.h>

#define BB 32
#define CC 273
#define TT 4096
#define OO 270
#define DD 242
#define NF 11
#define C_PAD 288   // padded C stride for embT
#define O_PAD 272   // padded O stride for hT / weights

// Scratch (device globals: allocation-free). Generous pads cover tile-edge
// cp.async address formation on the padded K/M/N ranges.
// Pre-split tf32 operands for the scores GEMM: _b = cvt.rna(x),
// _s = cvt.rna(x - _b). Produced once by embed/gather, consumed by scores.
__device__ __align__(16) float g_embT_b[(size_t)BB * DD * C_PAD + 8192]; // [b][d][c]
__device__ __align__(16) float g_embT_s[(size_t)BB * DD * C_PAD + 8192];
__device__ __align__(16) float g_hT_b  [(size_t)BB * DD * O_PAD + 8192]; // [b][d][o]
__device__ __align__(16) float g_hT_s  [(size_t)BB * DD * O_PAD + 8192];
__device__ __align__(16) float g_w     [(size_t)BB * CC * O_PAD + 16384]; // [b][c][o]
__device__ float g_off[(size_t)BB * CC];

__device__ __forceinline__ uint32_t f2tf32(float f) {
    uint32_t r;
    asm("cvt.rna.tf32.f32 %0, %1;" : "=r"(r) : "f"(f));
    return r;
}

__device__ __forceinline__ void cp16(uint32_t dst, const void* src, bool pred) {
    int sz = pred ? 16 : 0;
    asm volatile("cp.async.cg.shared.global [%0], [%1], 16, %2;"
                 :: "r"(dst), "l"(src), "r"(sz) : "memory");
}

#define MMA_TF32(acc, a0, a1, a2, a3, b0, b1)                                \
    asm volatile(                                                            \
        "mma.sync.aligned.m16n8k8.row.col.f32.tf32.tf32.f32 "                \
        "{%0,%1,%2,%3}, {%4,%5,%6,%7}, {%8,%9}, {%0,%1,%2,%3};"              \
        : "+f"((acc)[0]), "+f"((acc)[1]), "+f"((acc)[2]), "+f"((acc)[3])     \
        : "r"(a0), "r"(a1), "r"(a2), "r"(a3), "r"(b0), "r"(b1))

// ---------------------------------------------------------------------------
// Kernel 1: Fourier embedding, transposed [b][d][c], pre-split tf32 pair,
// + invalid offset.
// ---------------------------------------------------------------------------
__global__ void embed_kernel(const float* __restrict__ pos) {
    int b = blockIdx.y;
    int c = blockIdx.x * 32 + threadIdx.x;
    if (c >= CC) return;
    float x = pos[((size_t)b * CC + c) * 2 + 0];
    float y = pos[((size_t)b * CC + c) * 2 + 1];
    if (threadIdx.y == 0) {
        g_off[(size_t)b * CC + c] = (x == -0.1f && y == -0.1f) ? -1e9f : 0.0f;
    }
    const float scale = (float)(2.0 * 3.14159265358979323846 / 1.4);
    float px = x + 0.2f, py = y + 0.2f;
    float* ebB = g_embT_b + (size_t)b * (DD * C_PAD);
    float* ebS = g_embT_s + (size_t)b * (DD * C_PAD);
    for (int k = threadIdx.y; k < NF * NF; k += blockDim.y) {
        int i = k / NF, j = k % NF;
        float loc = px * (scale * (float)i) + py * (scale * (float)j);
        float s, co;
        sincosf(loc, &s, &co);
        float cb = __uint_as_float(f2tf32(co));
        float sb = __uint_as_float(f2tf32(s));
        ebB[(size_t)k * C_PAD + c] = cb;
        ebS[(size_t)k * C_PAD + c] = __uint_as_float(f2tf32(co - cb));
        ebB[(size_t)(NF * NF + k) * C_PAD + c] = sb;
        ebS[(size_t)(NF * NF + k) * C_PAD + c] = __uint_as_float(f2tf32(s - sb));
    }
}

// ---------------------------------------------------------------------------
// Kernel 2: heads gather + transpose -> pre-split hT[b][d][o]
// ---------------------------------------------------------------------------
__global__ void gather_heads_kernel(const float* __restrict__ heads,
                                    const int* __restrict__ subj) {
    __shared__ float tile[32][33];
    int b = blockIdx.z;
    int s = subj[b];
    int d0 = blockIdx.x * 32;
    int o0 = blockIdx.y * 32;
    const float* hb = heads + (size_t)s * OO * DD;
    for (int oy = threadIdx.y; oy < 32; oy += blockDim.y) {
        int o = o0 + oy;
        int d = d0 + threadIdx.x;
        tile[oy][threadIdx.x] = (o < OO && d < DD) ? hb[(size_t)o * DD + d] : 0.0f;
    }
    __syncthreads();
    float* htB = g_hT_b + (size_t)b * (DD * O_PAD);
    float* htS = g_hT_s + (size_t)b * (DD * O_PAD);
    for (int dy = threadIdx.y; dy < 32; dy += blockDim.y) {
        int d = d0 + dy;
        int o = o0 + threadIdx.x;
        if (d < DD && o < OO) {
            float v = tile[threadIdx.x][dy];
            float vb = __uint_as_float(f2tf32(v));
            htB[(size_t)d * O_PAD + o] = vb;
            htS[(size_t)d * O_PAD + o] = __uint_as_float(f2tf32(v - vb));
        }
    }
}

// ---------------------------------------------------------------------------
// Kernel 3: scores via 3xTF32 tensor cores, PRE-SPLIT operands (no cvt in
// the mainloop — pure LDS+MMA).
// g_w[b][c][o] = sum_d embT[b][d][c] * hT[b][d][o] + off[b][c]
// M=273, N=270, K=242. BM=BN=64, BK=16; 128 thr, warps 2Mx2N, tile 32x32.
// Dynamic SMEM: 4 arrays [3][16][72] u32 = 55296 B.
// ---------------------------------------------------------------------------
#define S_BM 64
#define S_BN 64
#define S_BK 16
#define S_STR 72
#define S_NT ((DD + S_BK - 1) / S_BK)   // 16
#define S_ARR (3 * S_BK * S_STR)        // 3456 u32 per array
#define S_SMEM_BYTES (4 * S_ARR * 4)    // 55296 B

__global__ __launch_bounds__(128) void scores_kernel(
    const float* __restrict__ AB, const float* __restrict__ AS,
    const float* __restrict__ BBp, const float* __restrict__ BSp,
    float* __restrict__ C, const float* __restrict__ off) {
    extern __shared__ uint32_t smem[];
    uint32_t* AsB = smem;
    uint32_t* AsS = smem + S_ARR;
    uint32_t* BsB = smem + 2 * S_ARR;
    uint32_t* BsS = smem + 3 * S_ARR;

    int b = blockIdx.z;
    const float* AbB = AB + (size_t)b * ((size_t)DD * C_PAD);
    const float* AbS = AS + (size_t)b * ((size_t)DD * C_PAD);
    const float* BbB = BBp + (size_t)b * ((size_t)DD * O_PAD);
    const float* BbS = BSp + (size_t)b * ((size_t)DD * O_PAD);
    float* Cb = C + (size_t)b * ((size_t)CC * O_PAD);

    int m0 = blockIdx.y * S_BM;
    int n0 = blockIdx.x * S_BN;
    int tid = threadIdx.x;
    int warpId = tid >> 5;
    int lane = tid & 31;
    int warpM = warpId & 1;
    int warpN = warpId >> 1;
    int groupID = lane >> 2;
    int tig = lane & 3;

    int kq[2], mq[2];
#pragma unroll
    for (int r = 0; r < 2; r++) {
        int ia = (tid + r * 128) * 4;
        kq[r] = ia / S_BM; mq[r] = ia % S_BM;
    }

    float acc[2][4][4];
#pragma unroll
    for (int mt = 0; mt < 2; mt++)
#pragma unroll
        for (int nt = 0; nt < 4; nt++)
#pragma unroll
            for (int r = 0; r < 4; r++) acc[mt][nt][r] = 0.0f;

    auto issue = [&](int kt, int stage) {
        int k0 = kt * S_BK;
        uint32_t base = stage * (S_BK * S_STR);
#pragma unroll
        for (int r = 0; r < 2; r++) {
            bool p = (k0 + kq[r]) < DD;
            size_t aoff = (size_t)(k0 + kq[r]) * C_PAD + m0 + mq[r];
            size_t boff = (size_t)(k0 + kq[r]) * O_PAD + n0 + mq[r];
            uint32_t soff = base + kq[r] * S_STR + mq[r];
            cp16(__cvta_generic_to_shared(&AsB[soff]), AbB + aoff, p);
            cp16(__cvta_generic_to_shared(&AsS[soff]), AbS + aoff, p);
            cp16(__cvta_generic_to_shared(&BsB[soff]), BbB + boff, p);
            cp16(__cvta_generic_to_shared(&BsS[soff]), BbS + boff, p);
        }
    };

    issue(0, 0);
    asm volatile("cp.async.commit_group;" ::: "memory");
    issue(1, 1);
    asm volatile("cp.async.commit_group;" ::: "memory");

    for (int kt = 0; kt < S_NT; kt++) {
        int stage = kt % 3;
        if (kt + 2 < S_NT) issue(kt + 2, (kt + 2) % 3);
        asm volatile("cp.async.commit_group;" ::: "memory");
        asm volatile("cp.async.wait_group 2;" ::: "memory");
        __syncthreads();

        uint32_t base = stage * (S_BK * S_STR);
#pragma unroll
        for (int kk = 0; kk < S_BK; kk += 8) {
            uint32_t aB[2][4], aS[2][4];
#pragma unroll
            for (int mt = 0; mt < 2; mt++) {
                int mb = warpM * 32 + mt * 16;
#pragma unroll
                for (int q = 0; q < 4; q++) {
                    int kr = kk + tig + (q >> 1) * 4;
                    int mc = mb + groupID + (q & 1) * 8;
                    aB[mt][q] = AsB[base + kr * S_STR + mc];
                    aS[mt][q] = AsS[base + kr * S_STR + mc];
                }
            }
            uint32_t bB[4][2], bS[4][2];
#pragma unroll
            for (int nt = 0; nt < 4; nt++) {
                int nb = warpN * 32 + nt * 8;
#pragma unroll
                for (int q = 0; q < 2; q++) {
                    int kr = kk + tig + q * 4;
                    bB[nt][q] = BsB[base + kr * S_STR + nb + groupID];
                    bS[nt][q] = BsS[base + kr * S_STR + nb + groupID];
                }
            }
#pragma unroll
            for (int mt = 0; mt < 2; mt++)
#pragma unroll
                for (int nt = 0; nt < 4; nt++) {
                    MMA_TF32(acc[mt][nt], aB[mt][0], aB[mt][1], aB[mt][2], aB[mt][3],
                             bS[nt][0], bS[nt][1]);
                    MMA_TF32(acc[mt][nt], aS[mt][0], aS[mt][1], aS[mt][2], aS[mt][3],
                             bB[nt][0], bB[nt][1]);
                    MMA_TF32(acc[mt][nt], aB[mt][0], aB[mt][1], aB[mt][2], aB[mt][3],
                             bB[nt][0], bB[nt][1]);
                }
        }
        __syncthreads();
    }

#pragma unroll
    for (int mt = 0; mt < 2; mt++) {
        int mrow0 = m0 + warpM * 32 + mt * 16 + groupID;
#pragma unroll
        for (int nt = 0; nt < 4; nt++) {
            int ncol = n0 + warpN * 32 + nt * 8 + tig * 2;
#pragma unroll
            for (int h = 0; h < 2; h++) {
                int m = mrow0 + h * 8;
                if (m < CC) {
                    float ofs = off[(size_t)b * CC + m];
                    if (ncol < OO)
                        Cb[(size_t)m * O_PAD + ncol] = acc[mt][nt][h * 2] + ofs;
                    if (ncol + 1 < OO)
                        Cb[(size_t)m * O_PAD + ncol + 1] = acc[mt][nt][h * 2 + 1] + ofs;
                }
            }
        }
    }
}

// ---------------------------------------------------------------------------
// Kernel 4: softmax over c per (b,o), in place. Block (32 o, 32 c-slices).
// Weights written PRE-ROUNDED to tf32 (A operand of big GEMM passes raw).
// ---------------------------------------------------------------------------
__global__ __launch_bounds__(1024) void softmax_kernel() {
    __shared__ float red[32][33];
    int b = blockIdx.y;
    int tx = threadIdx.x;
    int ty = threadIdx.y;
    int o = blockIdx.x * 32 + tx;
    bool active = (o < OO);
    float* col = g_w + (size_t)b * (CC * O_PAD) + (active ? o : 0);

    float mx = -3.0e38f;
#pragma unroll
    for (int c = ty; c < CC; c += 32)
        if (active) mx = fmaxf(mx, col[(size_t)c * O_PAD]);
    red[ty][tx] = mx;
    __syncthreads();
    if (ty == 0) {
#pragma unroll
        for (int r = 1; r < 32; r++) mx = fmaxf(mx, red[r][tx]);
        red[0][tx] = mx;
    }
    __syncthreads();
    mx = red[0][tx];
    __syncthreads();

    float s = 0.0f;
    float e_loc[9];                // ceil(273/32) = 9
    int ns = 0;
#pragma unroll
    for (int c = ty; c < CC; c += 32) {
        if (active) {
            float e = expf(col[(size_t)c * O_PAD] - mx);
            e_loc[ns] = e;
            s += e;
        }
        ns++;
    }
    red[ty][tx] = s;
    __syncthreads();
    if (ty == 0) {
#pragma unroll
        for (int r = 1; r < 32; r++) s += red[r][tx];
        red[0][tx] = 1.0f / s;
    }
    __syncthreads();
    float inv = red[0][tx];

    ns = 0;
#pragma unroll
    for (int c = ty; c < CC; c += 32) {
        if (active)
            col[(size_t)c * O_PAD] = __uint_as_float(f2tf32(e_loc[ns] * inv));
        ns++;
    }
}

// ---------------------------------------------------------------------------
// Kernel 5: TF32 tensor-core GEMM — the measured-185us R13 configuration,
// restored verbatim. BM=96/BN=128/BK=16, 128 thr, 3-stage cp.async,
// 3 blocks/SM. (BN=256 and BM=288 both regressed: this kernel is
// pipeline/occupancy-bound, not L2-traffic-bound.)
// ---------------------------------------------------------------------------
#define TBM 96
#define TBN 128
#define TBK 16
#define A_STR 104
#define B_STR 136
#define NTILES ((CC + TBK - 1) / TBK)   // 18

__global__ __launch_bounds__(128, 3) void gemm_tf32_kernel(
    const float* __restrict__ A, const float* __restrict__ B,
    float* __restrict__ C) {
    __shared__ uint32_t As[3][TBK][A_STR];
    __shared__ uint32_t Bs[3][TBK][B_STR];

    int b = blockIdx.z;
    const float* Ab = A + (size_t)b * ((size_t)CC * O_PAD);
    const float* Bb = B + (size_t)b * ((size_t)CC * TT);
    float* Cb = C + (size_t)b * ((size_t)OO * TT);

    int m0 = blockIdx.y * TBM;
    int n0 = blockIdx.x * TBN;
    int tid = threadIdx.x;
    int warpN = tid >> 5;
    int lane = tid & 31;
    int groupID = lane >> 2;
    int tig = lane & 3;

    int ka[3], ma[3], kb[4], nb[4];
#pragma unroll
    for (int r = 0; r < 3; r++) {
        int ia = (tid + r * 128) * 4;
        ka[r] = ia / TBM; ma[r] = ia % TBM;
    }
#pragma unroll
    for (int r = 0; r < 4; r++) {
        int ib = (tid + r * 128) * 4;
        kb[r] = ib / TBN; nb[r] = ib % TBN;
    }

    float acc[6][4][4];
#pragma unroll
    for (int mt = 0; mt < 6; mt++)
#pragma unroll
        for (int nt = 0; nt < 4; nt++)
#pragma unroll
            for (int r = 0; r < 4; r++) acc[mt][nt][r] = 0.0f;

    auto issue_tile = [&](int kt, int stage) {
        int k0 = kt * TBK;
#pragma unroll
        for (int r = 0; r < 3; r++)
            cp16(__cvta_generic_to_shared(&As[stage][ka[r]][ma[r]]),
                 Ab + (size_t)(k0 + ka[r]) * O_PAD + m0 + ma[r], (k0 + ka[r]) < CC);
#pragma unroll
        for (int r = 0; r < 4; r++)
            cp16(__cvta_generic_to_shared(&Bs[stage][kb[r]][nb[r]]),
                 Bb + (size_t)(k0 + kb[r]) * TT + n0 + nb[r], (k0 + kb[r]) < CC);
    };

    issue_tile(0, 0);
    asm volatile("cp.async.commit_group;" ::: "memory");
    issue_tile(1, 1);
    asm volatile("cp.async.commit_group;" ::: "memory");

    for (int kt = 0; kt < NTILES; kt++) {
        int stage = kt % 3;
        if (kt + 2 < NTILES) issue_tile(kt + 2, (kt + 2) % 3);
        asm volatile("cp.async.commit_group;" ::: "memory");
        asm volatile("cp.async.wait_group 2;" ::: "memory");
        __syncthreads();

#pragma unroll
        for (int kk = 0; kk < TBK; kk += 8) {
            uint32_t afrag[6][4];
#pragma unroll
            for (int mt = 0; mt < 6; mt++) {
                int mb = mt * 16;
                afrag[mt][0] = As[stage][kk + tig][mb + groupID];
                afrag[mt][1] = As[stage][kk + tig][mb + groupID + 8];
                afrag[mt][2] = As[stage][kk + tig + 4][mb + groupID];
                afrag[mt][3] = As[stage][kk + tig + 4][mb + groupID + 8];
            }
            uint32_t bfrag[4][2];
#pragma unroll
            for (int nt = 0; nt < 4; nt++) {
                int nbase = warpN * 32 + nt * 8;
                bfrag[nt][0] = f2tf32(__uint_as_float(Bs[stage][kk + tig][nbase + groupID]));
                bfrag[nt][1] = f2tf32(__uint_as_float(Bs[stage][kk + tig + 4][nbase + groupID]));
            }
#pragma unroll
            for (int mt = 0; mt < 6; mt++)
#pragma unroll
                for (int nt = 0; nt < 4; nt++)
                    MMA_TF32(acc[mt][nt], afrag[mt][0], afrag[mt][1],
                             afrag[mt][2], afrag[mt][3],
                             bfrag[nt][0], bfrag[nt][1]);
        }
        __syncthreads();
    }

#pragma unroll
    for (int mt = 0; mt < 6; mt++) {
        int mrow0 = m0 + mt * 16 + groupID;
#pragma unroll
        for (int nt = 0; nt < 4; nt++) {
            int ncol = n0 + warpN * 32 + nt * 8 + tig * 2;
            if (mrow0 < OO) {
                float2 v = make_float2(acc[mt][nt][0], acc[mt][nt][1]);
                *(float2*)(Cb + (size_t)mrow0 * TT + ncol) = v;
            }
            if (mrow0 + 8 < OO) {
                float2 v = make_float2(acc[mt][nt][2], acc[mt][nt][3]);
                *(float2*)(Cb + (size_t)(mrow0 + 8) * TT + ncol) = v;
            }
        }
    }
}

// ---------------------------------------------------------------------------

extern "C" void kernel_launch(void* const* d_in, const int* in_sizes, int n_in,
                              void* d_out, int out_size) {
    const float* meg   = (const float*)d_in[0];   // [B,C,T]
    const float* pos   = (const float*)d_in[1];   // [B,C,2]
    const int*   subj  = (const int*)d_in[2];     // [B]
    const float* heads = (const float*)d_in[3];   // [200,O,D]
    float* out = (float*)d_out;                   // [B,O,T]

    float *p_ebB, *p_ebS, *p_htB, *p_htS, *p_w, *p_off;
    cudaGetSymbolAddress((void**)&p_ebB, g_embT_b);
    cudaGetSymbolAddress((void**)&p_ebS, g_embT_s);
    cudaGetSymbolAddress((void**)&p_htB, g_hT_b);
    cudaGetSymbolAddress((void**)&p_htS, g_hT_s);
    cudaGetSymbolAddress((void**)&p_w,   g_w);
    cudaGetSymbolAddress((void**)&p_off, g_off);

    // >48KB dynamic SMEM opt-in for the scores kernel (idempotent host-side
    // attribute set; not a stream op, graph capture unaffected).
    cudaFuncSetAttribute(scores_kernel,
                         cudaFuncAttributeMaxDynamicSharedMemorySize,
                         S_SMEM_BYTES);

    // 1) Fourier embedding (transposed, pre-split tf32) + invalid offsets
    embed_kernel<<<dim3((CC + 31) / 32, BB), dim3(32, 8)>>>(pos);

    // 2) heads gather + transpose (pre-split tf32)
    gather_heads_kernel<<<dim3((DD + 31) / 32, (OO + 31) / 32, BB), dim3(32, 8)>>>(heads, subj);

    // 3) scores via 3xTF32 tensor cores, pre-split operands
    scores_kernel<<<dim3((OO + S_BN - 1) / S_BN, (CC + S_BM - 1) / S_BM, BB),
                    128, S_SMEM_BYTES>>>(
        p_ebB, p_ebS, p_htB, p_htS, p_w, p_off);

    // 4) softmax over c per (b,o), weights written tf32-rounded
    softmax_kernel<<<dim3((OO + 31) / 32, BB), dim3(32, 32)>>>();

    // 5) out[b][o][t] = sum_c w[b][c][o] * meg[b][c][t]  -- TF32, BM=96/BN=128
    gemm_tf32_kernel<<<dim3(TT / TBN, (OO + TBM - 1) / TBM, BB), 128>>>(
        p_w, meg, out);
}